// round 13
// baseline (speedup 1.0000x reference)
#include <cuda_runtime.h>
#include <math_constants.h>
#include <cstdint>

#define B_  4
#define S_  2048
#define H_  768
#define NH_ 12
#define D_  64
#define NZ_ 3          // KV splits

typedef unsigned long long ull;

__device__ float g_Q[B_*NH_*S_*D_];
__device__ float g_K[B_*NH_*S_*D_];
__device__ float g_V[B_*NH_*S_*D_];
__device__ float g_PO[NZ_ * B_*NH_ * S_ * D_];   // partial unnormalized O
__device__ float g_PL[NZ_ * B_*NH_ * S_];        // partial row sums

// ---------------- packed fp32x2 helpers ----------------
__device__ __forceinline__ ull pk2(float lo, float hi) {
    ull r; asm("mov.b64 %0, {%1, %2};" : "=l"(r) : "f"(lo), "f"(hi)); return r;
}
__device__ __forceinline__ void upk2(ull v, float& lo, float& hi) {
    asm("mov.b64 {%0, %1}, %2;" : "=f"(lo), "=f"(hi) : "l"(v));
}
__device__ __forceinline__ ull fma2(ull a, ull b, ull c) {
    ull d; asm("fma.rn.f32x2 %0, %1, %2, %3;" : "=l"(d) : "l"(a), "l"(b), "l"(c)); return d;
}
__device__ __forceinline__ ull add2(ull a, ull b) {
    ull d; asm("add.rn.f32x2 %0, %1, %2;" : "=l"(d) : "l"(a), "l"(b)); return d;
}
__device__ __forceinline__ float ex2a(float x) {
    float r; asm("ex2.approx.f32 %0, %1;" : "=f"(r) : "f"(x)); return r;
}

// ---------------------------------------------------------------------------
// Kernel 1: fused grouped QKV projection, 16x8 thread tile, double-buffered.
// CTA tile 128x128, BK=8, 128 threads. grid (6, 64, 3). Unchanged from R12.
// ---------------------------------------------------------------------------
__global__ __launch_bounds__(128, 2) void qkv_kernel(
    const float* __restrict__ e1, const float* __restrict__ e2, const float* __restrict__ e3,
    const float* __restrict__ Wq, const float* __restrict__ bq,
    const float* __restrict__ Wk, const float* __restrict__ bk,
    const float* __restrict__ Wv, const float* __restrict__ bv)
{
    __shared__ float As[2][8][128];   // [k][row]
    __shared__ float Bs[2][8][128];   // [k][n]

    const int g = blockIdx.z;
    const float* X = (g == 0) ? e1 : (g == 1) ? e2 : e3;

    const int n0    = blockIdx.x * 128;
    const int sect  = n0 >> 8;
    const int nloc0 = n0 & 255;
    const float* W  = (sect == 0) ? Wq : (sect == 1) ? Wk : Wv;
    const float* bb = (sect == 0) ? bq : (sect == 1) ? bk : bv;
    float* Out      = (sect == 0) ? g_Q : (sect == 1) ? g_K : g_V;

    const int m0 = blockIdx.y * 128;

    const int tid = threadIdx.x;
    const int tx = tid & 15, ty = tid >> 4;   // ty 0..7
    const int cr = ty * 16;
    const int cc = tx * 8;

    ull acc2[16][4];
    #pragma unroll
    for (int i = 0; i < 16; i++)
        #pragma unroll
        for (int j = 0; j < 4; j++) acc2[i][j] = 0ull;

    const float* Xp = X + (size_t)(m0 + tid) * H_;
    const int bn8 = tx * 8;
    const int nlB = nloc0 + bn8;
    const int hB  = 4 * g + (nlB >> 6);
    const int dB  = nlB & 63;
    const float* Wp = W + (size_t)hB * (H_ * D_) + dB;

    const int NCH = H_ / 8;   // 96

    float4 a0 = *(const float4*)(Xp);
    float4 a1 = *(const float4*)(Xp + 4);
    float4 w0 = *(const float4*)(Wp + (size_t)ty * D_);
    float4 w1 = *(const float4*)(Wp + (size_t)ty * D_ + 4);
    As[0][0][tid] = a0.x; As[0][1][tid] = a0.y; As[0][2][tid] = a0.z; As[0][3][tid] = a0.w;
    As[0][4][tid] = a1.x; As[0][5][tid] = a1.y; As[0][6][tid] = a1.z; As[0][7][tid] = a1.w;
    *(float4*)&Bs[0][ty][bn8]     = w0;
    *(float4*)&Bs[0][ty][bn8 + 4] = w1;
    a0 = *(const float4*)(Xp + 8);
    a1 = *(const float4*)(Xp + 12);
    w0 = *(const float4*)(Wp + (size_t)(8 + ty) * D_);
    w1 = *(const float4*)(Wp + (size_t)(8 + ty) * D_ + 4);
    __syncthreads();

    #pragma unroll 1
    for (int ch = 0; ch < NCH; ch++) {
        const int cur = ch & 1;
        if (ch + 1 < NCH) {
            As[cur ^ 1][0][tid] = a0.x; As[cur ^ 1][1][tid] = a0.y;
            As[cur ^ 1][2][tid] = a0.z; As[cur ^ 1][3][tid] = a0.w;
            As[cur ^ 1][4][tid] = a1.x; As[cur ^ 1][5][tid] = a1.y;
            As[cur ^ 1][6][tid] = a1.z; As[cur ^ 1][7][tid] = a1.w;
            *(float4*)&Bs[cur ^ 1][ty][bn8]     = w0;
            *(float4*)&Bs[cur ^ 1][ty][bn8 + 4] = w1;
        }
        if (ch + 2 < NCH) {
            const int k0 = (ch + 2) * 8;
            a0 = *(const float4*)(Xp + k0);
            a1 = *(const float4*)(Xp + k0 + 4);
            w0 = *(const float4*)(Wp + (size_t)(k0 + ty) * D_);
            w1 = *(const float4*)(Wp + (size_t)(k0 + ty) * D_ + 4);
        }

        #pragma unroll
        for (int kk = 0; kk < 8; kk++) {
            float a[16];
            *(float4*)(a)      = *(const float4*)&As[cur][kk][cr];
            *(float4*)(a + 4)  = *(const float4*)&As[cur][kk][cr + 4];
            *(float4*)(a + 8)  = *(const float4*)&As[cur][kk][cr + 8];
            *(float4*)(a + 12) = *(const float4*)&As[cur][kk][cr + 12];
            float4 b0 = *(const float4*)&Bs[cur][kk][cc];
            float4 b1 = *(const float4*)&Bs[cur][kk][cc + 4];
            ull bp[4];
            bp[0] = pk2(b0.x, b0.y); bp[1] = pk2(b0.z, b0.w);
            bp[2] = pk2(b1.x, b1.y); bp[3] = pk2(b1.z, b1.w);
            #pragma unroll
            for (int i = 0; i < 16; i++) {
                const ull ad = pk2(a[i], a[i]);
                #pragma unroll
                for (int j = 0; j < 4; j++)
                    acc2[i][j] = fma2(ad, bp[j], acc2[i][j]);
            }
        }
        __syncthreads();
    }

    const int nc = nloc0 + cc;
    const int eh = 4 * g + (nc >> 6);
    const int dc = nc & 63;
    float bias8[8];
    #pragma unroll
    for (int j = 0; j < 8; j++) bias8[j] = bb[eh * D_ + dc + j];

    #pragma unroll
    for (int i = 0; i < 16; i++) {
        const int rr   = m0 + cr + i;
        const int bi   = rr >> 11;
        const int srow = rr & 2047;
        float* op = Out + (((size_t)(bi * NH_ + eh)) * S_ + srow) * D_ + dc;
        float c[8];
        upk2(acc2[i][0], c[0], c[1]); upk2(acc2[i][1], c[2], c[3]);
        upk2(acc2[i][2], c[4], c[5]); upk2(acc2[i][3], c[6], c[7]);
        float4 v0, v1;
        v0.x = c[0] + bias8[0]; v0.y = c[1] + bias8[1];
        v0.z = c[2] + bias8[2]; v0.w = c[3] + bias8[3];
        v1.x = c[4] + bias8[4]; v1.y = c[5] + bias8[5];
        v1.z = c[6] + bias8[6]; v1.w = c[7] + bias8[7];
        *(float4*)(op)     = v0;
        *(float4*)(op + 4) = v1;
    }
}

// ---------------------------------------------------------------------------
// Kernel 2: flash attention, 8x8 thread tile, 128 threads, packed fp32x2,
// split-KV x3, raw exp2. Thread (tx 0..7, ty 0..15): 8q x 8t scores,
// 8q x 8d output. grid (16, 48, 3), smem 104448 B.
// ---------------------------------------------------------------------------
__global__ __launch_bounds__(128, 2) void attn_kernel()
{
    extern __shared__ float smf[];
    float* Qs  = smf;              // [128][68], pre-scaled by SCL*log2(e)
    float* KsT = Qs + 128 * 68;    // [64 d][68] (t contig)
    float* Vs  = KsT + 64 * 68;    // [64 t][68] (d contig)
    float* Ps  = Vs + 64 * 68;     // [128][68]

    const int bh = blockIdx.y;
    const int z  = blockIdx.z;
    const int q0 = blockIdx.x * 128;
    const size_t base = (size_t)bh * S_ * D_;
    const float *Qg = g_Q + base, *Kg = g_K + base, *Vg = g_V + base;

    const int tid = threadIdx.x;
    const int tx = tid & 7, ty = tid >> 3;   // tx 0..7, ty 0..15

    const float SCLL = 0.125f * 1.44269504f;   // 1/sqrt(D) * log2(e)
    for (int i = tid; i < 128 * 16; i += 128) {
        const int r = i >> 4, c4 = (i & 15) * 4;
        float4 v = *(const float4*)(Qg + (size_t)(q0 + r) * D_ + c4);
        v.x *= SCLL; v.y *= SCLL; v.z *= SCLL; v.w *= SCLL;
        *(float4*)&Qs[r * 68 + c4] = v;
    }

    ull O2[8][4];
    ull lsum2[8];
    #pragma unroll
    for (int i = 0; i < 8; i++) {
        lsum2[i] = 0ull;
        #pragma unroll
        for (int j = 0; j < 4; j++) O2[i][j] = 0ull;
    }

    const int tile_beg = (z == 0) ? 0 : (z == 1) ? 11 : 22;
    const int tile_end = (z == 0) ? 11 : (z == 1) ? 22 : 32;

    for (int tt0 = tile_beg; tt0 < tile_end; tt0++) {
        const int t0 = tt0 * 64;
        __syncthreads();
        for (int i = tid; i < 64 * 16; i += 128) {
            const int r = i >> 4, c4 = (i & 15) * 4;
            float4 kv = *(const float4*)(Kg + (size_t)(t0 + r) * D_ + c4);
            KsT[(c4 + 0) * 68 + r] = kv.x;
            KsT[(c4 + 1) * 68 + r] = kv.y;
            KsT[(c4 + 2) * 68 + r] = kv.z;
            KsT[(c4 + 3) * 68 + r] = kv.w;
            *(float4*)&Vs[r * 68 + c4] = *(const float4*)(Vg + (size_t)(t0 + r) * D_ + c4);
        }
        __syncthreads();

        // scores: s[i][0..3 packed] = Qscaled[8ty+i] . K[8tx .. 8tx+7]
        ull s2[8][4];
        #pragma unroll
        for (int i = 0; i < 8; i++)
            #pragma unroll
            for (int j = 0; j < 4; j++) s2[i][j] = 0ull;
        #pragma unroll 2
        for (int k4 = 0; k4 < 64; k4 += 4) {
            float4 q4[8];
            #pragma unroll
            for (int i = 0; i < 8; i++) q4[i] = *(const float4*)&Qs[(8 * ty + i) * 68 + k4];
            const float* qp = (const float*)q4;
            #pragma unroll
            for (int kk = 0; kk < 4; kk++) {
                float4 kv0 = *(const float4*)&KsT[(k4 + kk) * 68 + 8 * tx];
                float4 kv1 = *(const float4*)&KsT[(k4 + kk) * 68 + 8 * tx + 4];
                ull kp[4];
                kp[0] = pk2(kv0.x, kv0.y); kp[1] = pk2(kv0.z, kv0.w);
                kp[2] = pk2(kv1.x, kv1.y); kp[3] = pk2(kv1.z, kv1.w);
                #pragma unroll
                for (int i = 0; i < 8; i++) {
                    const float qs = qp[i * 4 + kk];
                    const ull qd = pk2(qs, qs);
                    #pragma unroll
                    for (int j = 0; j < 4; j++)
                        s2[i][j] = fma2(qd, kp[j], s2[i][j]);
                }
            }
        }

        // p = 2^s (raw), accumulate packed partial row sums
        #pragma unroll
        for (int i = 0; i < 8; i++) {
            #pragma unroll
            for (int j = 0; j < 4; j++) {
                float p0, p1;
                upk2(s2[i][j], p0, p1);
                p0 = ex2a(p0); p1 = ex2a(p1);
                s2[i][j] = pk2(p0, p1);
                lsum2[i] = add2(lsum2[i], s2[i][j]);
            }
        }

        // stage P (two 16B stores per row)
        #pragma unroll
        for (int i = 0; i < 8; i++) {
            ulonglong2 w0; w0.x = s2[i][0]; w0.y = s2[i][1];
            ulonglong2 w1; w1.x = s2[i][2]; w1.y = s2[i][3];
            *(ulonglong2*)&Ps[(8 * ty + i) * 68 + 8 * tx]     = w0;
            *(ulonglong2*)&Ps[(8 * ty + i) * 68 + 8 * tx + 4] = w1;
        }
        __syncthreads();

        // O += P * V  (unnormalized): O[8q][8d], d cols 8tx..8tx+7
        #pragma unroll 2
        for (int t4 = 0; t4 < 64; t4 += 4) {
            float4 p4[8];
            #pragma unroll
            for (int i = 0; i < 8; i++) p4[i] = *(const float4*)&Ps[(8 * ty + i) * 68 + t4];
            const float* pp = (const float*)p4;
            #pragma unroll
            for (int tt = 0; tt < 4; tt++) {
                float4 vv0 = *(const float4*)&Vs[(t4 + tt) * 68 + 8 * tx];
                float4 vv1 = *(const float4*)&Vs[(t4 + tt) * 68 + 8 * tx + 4];
                ull vp[4];
                vp[0] = pk2(vv0.x, vv0.y); vp[1] = pk2(vv0.z, vv0.w);
                vp[2] = pk2(vv1.x, vv1.y); vp[3] = pk2(vv1.z, vv1.w);
                #pragma unroll
                for (int i = 0; i < 8; i++) {
                    const float ps = pp[i * 4 + tt];
                    const ull pd = pk2(ps, ps);
                    #pragma unroll
                    for (int j = 0; j < 4; j++)
                        O2[i][j] = fma2(pd, vp[j], O2[i][j]);
                }
            }
        }
    }

    // Partial epilogue: reduce row sums over the 8 tx lanes, write raw O + sum.
    float* po = g_PO + ((size_t)(z * (B_ * NH_) + bh) * S_) * D_;
    float* pl = g_PL + (size_t)(z * (B_ * NH_) + bh) * S_;
    #pragma unroll
    for (int i = 0; i < 8; i++) {
        float l0, l1;
        upk2(lsum2[i], l0, l1);
        float rs = l0 + l1;
        rs += __shfl_xor_sync(0xffffffffu, rs, 1);
        rs += __shfl_xor_sync(0xffffffffu, rs, 2);
        rs += __shfl_xor_sync(0xffffffffu, rs, 4);
        const int srow = q0 + 8 * ty + i;
        float c[8];
        upk2(O2[i][0], c[0], c[1]); upk2(O2[i][1], c[2], c[3]);
        upk2(O2[i][2], c[4], c[5]); upk2(O2[i][3], c[6], c[7]);
        float4 v0; v0.x = c[0]; v0.y = c[1]; v0.z = c[2]; v0.w = c[3];
        float4 v1; v1.x = c[4]; v1.y = c[5]; v1.z = c[6]; v1.w = c[7];
        *(float4*)(po + (size_t)srow * D_ + 8 * tx)     = v0;
        *(float4*)(po + (size_t)srow * D_ + 8 * tx + 4) = v1;
        if (tx == 0) pl[srow] = rs;
    }
}

// ---------------------------------------------------------------------------
// Kernel 3: combine split-KV partials. out = (sum_z O_z) / (sum_z l_z).
// ---------------------------------------------------------------------------
__global__ __launch_bounds__(256) void reduce_kernel(float* __restrict__ out)
{
    const int idx = blockIdx.x * 256 + threadIdx.x;
    const int bh  = idx >> 15;
    const int rem = idx & 32767;
    const int s   = rem >> 4;
    const int d4  = (rem & 15) * 4;

    const size_t stride_o = (size_t)(B_ * NH_) * S_ * D_;
    const size_t stride_l = (size_t)(B_ * NH_) * S_;
    const size_t obase = ((size_t)bh * S_ + s) * D_ + d4;
    const size_t lbase = (size_t)bh * S_ + s;

    const float l = g_PL[lbase] + g_PL[stride_l + lbase] + g_PL[2 * stride_l + lbase];
    const float inv = 1.f / l;

    float4 a = *(const float4*)(g_PO + obase);
    float4 b = *(const float4*)(g_PO + stride_o + obase);
    float4 c = *(const float4*)(g_PO + 2 * stride_o + obase);

    float4 v;
    v.x = (a.x + b.x + c.x) * inv;
    v.y = (a.y + b.y + c.y) * inv;
    v.z = (a.z + b.z + c.z) * inv;
    v.w = (a.w + b.w + c.w) * inv;

    const int bi = bh / NH_, h = bh % NH_;
    *(float4*)(out + ((size_t)(bi * S_ + s)) * (NH_ * D_) + h * D_ + d4) = v;
}

// ---------------------------------------------------------------------------
extern "C" void kernel_launch(void* const* d_in, const int* in_sizes, int n_in,
                              void* d_out, int out_size)
{
    const float* e1 = (const float*)d_in[0];
    const float* e2 = (const float*)d_in[1];
    const float* e3 = (const float*)d_in[2];
    const float* Wq = (const float*)d_in[3];
    const float* bq = (const float*)d_in[4];
    const float* Wk = (const float*)d_in[5];
    const float* bk = (const float*)d_in[6];
    const float* Wv = (const float*)d_in[7];
    const float* bv = (const float*)d_in[8];
    float* out = (float*)d_out;

    const int attn_smem = (128 + 64 + 64 + 128) * 68 * 4;   // 104448
    cudaFuncSetAttribute(attn_kernel, cudaFuncAttributeMaxDynamicSharedMemorySize, attn_smem);

    dim3 ggrid(6, 64, 3);
    qkv_kernel<<<ggrid, 128>>>(e1, e2, e3, Wq, bq, Wk, bk, Wv, bv);

    dim3 agrid(S_ / 128, B_ * NH_, NZ_);
    attn_kernel<<<agrid, 128, attn_smem>>>();

    const int n4 = B_ * NH_ * S_ * (D_ / 4);     // 1572864
    reduce_kernel<<<n4 / 256, 256>>>(out);
}

// round 14
// speedup vs baseline: 1.0934x; 1.0934x over previous
#include <cuda_runtime.h>
#include <math_constants.h>
#include <cstdint>

#define B_  4
#define S_  2048
#define H_  768
#define NH_ 12
#define D_  64
#define NZ_ 3          // KV splits

typedef unsigned long long ull;

__device__ float g_Q[B_*NH_*S_*D_];
__device__ float g_K[B_*NH_*S_*D_];
__device__ float g_V[B_*NH_*S_*D_];
__device__ float g_PO[NZ_ * B_*NH_ * S_ * D_];   // partial unnormalized O
__device__ float g_PL[NZ_ * B_*NH_ * S_];        // partial row sums

// ---------------- packed fp32x2 helpers ----------------
__device__ __forceinline__ ull pk2(float lo, float hi) {
    ull r; asm("mov.b64 %0, {%1, %2};" : "=l"(r) : "f"(lo), "f"(hi)); return r;
}
__device__ __forceinline__ void upk2(ull v, float& lo, float& hi) {
    asm("mov.b64 {%0, %1}, %2;" : "=f"(lo), "=f"(hi) : "l"(v));
}
__device__ __forceinline__ ull fma2(ull a, ull b, ull c) {
    ull d; asm("fma.rn.f32x2 %0, %1, %2, %3;" : "=l"(d) : "l"(a), "l"(b), "l"(c)); return d;
}
__device__ __forceinline__ ull add2(ull a, ull b) {
    ull d; asm("add.rn.f32x2 %0, %1, %2;" : "=l"(d) : "l"(a), "l"(b)); return d;
}
__device__ __forceinline__ float ex2a(float x) {
    float r; asm("ex2.approx.f32 %0, %1;" : "=f"(r) : "f"(x)); return r;
}

// ---------------------------------------------------------------------------
// Kernel 1: fused grouped QKV projection, 16x8 thread tile, BK=16,
// double-buffered register prefetch. CTA tile 128x128, 128 threads.
// grid (6, 64, 3). One __syncthreads per 16-k chunk (48 total).
// ---------------------------------------------------------------------------
__global__ __launch_bounds__(128, 2) void qkv_kernel(
    const float* __restrict__ e1, const float* __restrict__ e2, const float* __restrict__ e3,
    const float* __restrict__ Wq, const float* __restrict__ bq,
    const float* __restrict__ Wk, const float* __restrict__ bk,
    const float* __restrict__ Wv, const float* __restrict__ bv)
{
    __shared__ float As[2][16][128];   // [k][row]
    __shared__ float Bs[2][16][128];   // [k][n]

    const int g = blockIdx.z;
    const float* X = (g == 0) ? e1 : (g == 1) ? e2 : e3;

    const int n0    = blockIdx.x * 128;
    const int sect  = n0 >> 8;
    const int nloc0 = n0 & 255;
    const float* W  = (sect == 0) ? Wq : (sect == 1) ? Wk : Wv;
    const float* bb = (sect == 0) ? bq : (sect == 1) ? bk : bv;
    float* Out      = (sect == 0) ? g_Q : (sect == 1) ? g_K : g_V;

    const int m0 = blockIdx.y * 128;

    const int tid = threadIdx.x;
    const int tx = tid & 15, ty = tid >> 4;   // ty 0..7
    const int cr = ty * 16;
    const int cc = tx * 8;

    ull acc2[16][4];
    #pragma unroll
    for (int i = 0; i < 16; i++)
        #pragma unroll
        for (int j = 0; j < 4; j++) acc2[i][j] = 0ull;

    // A: one row per thread, 16 k-floats = 4 float4 per chunk.
    const float* Xp = X + (size_t)(m0 + tid) * H_;
    // B: thread loads k-rows ty and ty+8 of the chunk, 8 n-floats each.
    const int bn8 = tx * 8;
    const int nlB = nloc0 + bn8;
    const int hB  = 4 * g + (nlB >> 6);
    const int dB  = nlB & 63;
    const float* Wp = W + (size_t)hB * (H_ * D_) + dB;

    const int NCH = H_ / 16;   // 48

    // Prologue: chunk 0 -> buf 0; prefetch chunk 1 into regs.
    float4 a0 = *(const float4*)(Xp);
    float4 a1 = *(const float4*)(Xp + 4);
    float4 a2 = *(const float4*)(Xp + 8);
    float4 a3 = *(const float4*)(Xp + 12);
    float4 w00 = *(const float4*)(Wp + (size_t)ty * D_);
    float4 w01 = *(const float4*)(Wp + (size_t)ty * D_ + 4);
    float4 w10 = *(const float4*)(Wp + (size_t)(ty + 8) * D_);
    float4 w11 = *(const float4*)(Wp + (size_t)(ty + 8) * D_ + 4);
    As[0][ 0][tid] = a0.x; As[0][ 1][tid] = a0.y; As[0][ 2][tid] = a0.z; As[0][ 3][tid] = a0.w;
    As[0][ 4][tid] = a1.x; As[0][ 5][tid] = a1.y; As[0][ 6][tid] = a1.z; As[0][ 7][tid] = a1.w;
    As[0][ 8][tid] = a2.x; As[0][ 9][tid] = a2.y; As[0][10][tid] = a2.z; As[0][11][tid] = a2.w;
    As[0][12][tid] = a3.x; As[0][13][tid] = a3.y; As[0][14][tid] = a3.z; As[0][15][tid] = a3.w;
    *(float4*)&Bs[0][ty][bn8]         = w00;
    *(float4*)&Bs[0][ty][bn8 + 4]     = w01;
    *(float4*)&Bs[0][ty + 8][bn8]     = w10;
    *(float4*)&Bs[0][ty + 8][bn8 + 4] = w11;
    a0 = *(const float4*)(Xp + 16);
    a1 = *(const float4*)(Xp + 20);
    a2 = *(const float4*)(Xp + 24);
    a3 = *(const float4*)(Xp + 28);
    w00 = *(const float4*)(Wp + (size_t)(16 + ty) * D_);
    w01 = *(const float4*)(Wp + (size_t)(16 + ty) * D_ + 4);
    w10 = *(const float4*)(Wp + (size_t)(16 + ty + 8) * D_);
    w11 = *(const float4*)(Wp + (size_t)(16 + ty + 8) * D_ + 4);
    __syncthreads();

    #pragma unroll 1
    for (int ch = 0; ch < NCH; ch++) {
        const int cur = ch & 1;
        if (ch + 1 < NCH) {
            As[cur ^ 1][ 0][tid] = a0.x; As[cur ^ 1][ 1][tid] = a0.y;
            As[cur ^ 1][ 2][tid] = a0.z; As[cur ^ 1][ 3][tid] = a0.w;
            As[cur ^ 1][ 4][tid] = a1.x; As[cur ^ 1][ 5][tid] = a1.y;
            As[cur ^ 1][ 6][tid] = a1.z; As[cur ^ 1][ 7][tid] = a1.w;
            As[cur ^ 1][ 8][tid] = a2.x; As[cur ^ 1][ 9][tid] = a2.y;
            As[cur ^ 1][10][tid] = a2.z; As[cur ^ 1][11][tid] = a2.w;
            As[cur ^ 1][12][tid] = a3.x; As[cur ^ 1][13][tid] = a3.y;
            As[cur ^ 1][14][tid] = a3.z; As[cur ^ 1][15][tid] = a3.w;
            *(float4*)&Bs[cur ^ 1][ty][bn8]         = w00;
            *(float4*)&Bs[cur ^ 1][ty][bn8 + 4]     = w01;
            *(float4*)&Bs[cur ^ 1][ty + 8][bn8]     = w10;
            *(float4*)&Bs[cur ^ 1][ty + 8][bn8 + 4] = w11;
        }
        if (ch + 2 < NCH) {
            const int k0 = (ch + 2) * 16;
            a0 = *(const float4*)(Xp + k0);
            a1 = *(const float4*)(Xp + k0 + 4);
            a2 = *(const float4*)(Xp + k0 + 8);
            a3 = *(const float4*)(Xp + k0 + 12);
            w00 = *(const float4*)(Wp + (size_t)(k0 + ty) * D_);
            w01 = *(const float4*)(Wp + (size_t)(k0 + ty) * D_ + 4);
            w10 = *(const float4*)(Wp + (size_t)(k0 + ty + 8) * D_);
            w11 = *(const float4*)(Wp + (size_t)(k0 + ty + 8) * D_ + 4);
        }

        #pragma unroll
        for (int kk = 0; kk < 16; kk++) {
            float a[16];
            *(float4*)(a)      = *(const float4*)&As[cur][kk][cr];
            *(float4*)(a + 4)  = *(const float4*)&As[cur][kk][cr + 4];
            *(float4*)(a + 8)  = *(const float4*)&As[cur][kk][cr + 8];
            *(float4*)(a + 12) = *(const float4*)&As[cur][kk][cr + 12];
            float4 b0 = *(const float4*)&Bs[cur][kk][cc];
            float4 b1 = *(const float4*)&Bs[cur][kk][cc + 4];
            ull bp[4];
            bp[0] = pk2(b0.x, b0.y); bp[1] = pk2(b0.z, b0.w);
            bp[2] = pk2(b1.x, b1.y); bp[3] = pk2(b1.z, b1.w);
            #pragma unroll
            for (int i = 0; i < 16; i++) {
                const ull ad = pk2(a[i], a[i]);
                #pragma unroll
                for (int j = 0; j < 4; j++)
                    acc2[i][j] = fma2(ad, bp[j], acc2[i][j]);
            }
        }
        __syncthreads();
    }

    const int nc = nloc0 + cc;
    const int eh = 4 * g + (nc >> 6);
    const int dc = nc & 63;
    float bias8[8];
    #pragma unroll
    for (int j = 0; j < 8; j++) bias8[j] = bb[eh * D_ + dc + j];

    #pragma unroll
    for (int i = 0; i < 16; i++) {
        const int rr   = m0 + cr + i;
        const int bi   = rr >> 11;
        const int srow = rr & 2047;
        float* op = Out + (((size_t)(bi * NH_ + eh)) * S_ + srow) * D_ + dc;
        float c[8];
        upk2(acc2[i][0], c[0], c[1]); upk2(acc2[i][1], c[2], c[3]);
        upk2(acc2[i][2], c[4], c[5]); upk2(acc2[i][3], c[6], c[7]);
        float4 v0, v1;
        v0.x = c[0] + bias8[0]; v0.y = c[1] + bias8[1];
        v0.z = c[2] + bias8[2]; v0.w = c[3] + bias8[3];
        v1.x = c[4] + bias8[4]; v1.y = c[5] + bias8[5];
        v1.z = c[6] + bias8[6]; v1.w = c[7] + bias8[7];
        *(float4*)(op)     = v0;
        *(float4*)(op + 4) = v1;
    }
}

// ---------------------------------------------------------------------------
// Kernel 2: flash attention, packed fp32x2, split-KV x3, raw exp2.
// REVERTED to the proven 8x4 tile / 256-thread config (R9).
// grid (16, 48, 3), smem 104448 B.
// ---------------------------------------------------------------------------
__global__ __launch_bounds__(256, 2) void attn_kernel()
{
    extern __shared__ float smf[];
    float* Qs  = smf;              // [128][68], pre-scaled by SCL*log2(e)
    float* KsT = Qs + 128 * 68;    // [64 d][68] (t contig)
    float* Vs  = KsT + 64 * 68;    // [64 t][68] (d contig)
    float* Ps  = Vs + 64 * 68;     // [128][68]

    const int bh = blockIdx.y;
    const int z  = blockIdx.z;
    const int q0 = blockIdx.x * 128;
    const size_t base = (size_t)bh * S_ * D_;
    const float *Qg = g_Q + base, *Kg = g_K + base, *Vg = g_V + base;

    const int tid = threadIdx.x;
    const int tx = tid & 15, ty = tid >> 4;

    const float SCLL = 0.125f * 1.44269504f;   // 1/sqrt(D) * log2(e)
    for (int i = tid; i < 128 * 16; i += 256) {
        const int r = i >> 4, c4 = (i & 15) * 4;
        float4 v = *(const float4*)(Qg + (size_t)(q0 + r) * D_ + c4);
        v.x *= SCLL; v.y *= SCLL; v.z *= SCLL; v.w *= SCLL;
        *(float4*)&Qs[r * 68 + c4] = v;
    }

    ull O2[8][2];
    ull lsum2[8];
    #pragma unroll
    for (int i = 0; i < 8; i++) {
        lsum2[i] = 0ull;
        O2[i][0] = 0ull; O2[i][1] = 0ull;
    }

    const int tile_beg = (z == 0) ? 0 : (z == 1) ? 11 : 22;
    const int tile_end = (z == 0) ? 11 : (z == 1) ? 22 : 32;

    for (int tt0 = tile_beg; tt0 < tile_end; tt0++) {
        const int t0 = tt0 * 64;
        __syncthreads();
        for (int i = tid; i < 64 * 16; i += 256) {
            const int r = i >> 4, c4 = (i & 15) * 4;
            float4 kv = *(const float4*)(Kg + (size_t)(t0 + r) * D_ + c4);
            KsT[(c4 + 0) * 68 + r] = kv.x;
            KsT[(c4 + 1) * 68 + r] = kv.y;
            KsT[(c4 + 2) * 68 + r] = kv.z;
            KsT[(c4 + 3) * 68 + r] = kv.w;
            *(float4*)&Vs[r * 68 + c4] = *(const float4*)(Vg + (size_t)(t0 + r) * D_ + c4);
        }
        __syncthreads();

        // scores (log2-scaled): s[i][j] = Qscaled[8ty+i] . K[4tx+j]
        ull s2[8][2];
        #pragma unroll
        for (int i = 0; i < 8; i++) { s2[i][0] = 0ull; s2[i][1] = 0ull; }
        #pragma unroll 2
        for (int k4 = 0; k4 < 64; k4 += 4) {
            float4 q4[8];
            #pragma unroll
            for (int i = 0; i < 8; i++) q4[i] = *(const float4*)&Qs[(8 * ty + i) * 68 + k4];
            const float* qp = (const float*)q4;
            #pragma unroll
            for (int kk = 0; kk < 4; kk++) {
                float4 kvv = *(const float4*)&KsT[(k4 + kk) * 68 + 4 * tx];
                const ull klo = pk2(kvv.x, kvv.y), khi = pk2(kvv.z, kvv.w);
                #pragma unroll
                for (int i = 0; i < 8; i++) {
                    const float qs = qp[i * 4 + kk];
                    const ull qd = pk2(qs, qs);
                    s2[i][0] = fma2(qd, klo, s2[i][0]);
                    s2[i][1] = fma2(qd, khi, s2[i][1]);
                }
            }
        }

        // p = 2^s (raw), accumulate packed partial row sums
        #pragma unroll
        for (int i = 0; i < 8; i++) {
            float p0, p1, p2, p3;
            upk2(s2[i][0], p0, p1); upk2(s2[i][1], p2, p3);
            p0 = ex2a(p0); p1 = ex2a(p1);
            p2 = ex2a(p2); p3 = ex2a(p3);
            s2[i][0] = pk2(p0, p1); s2[i][1] = pk2(p2, p3);
            lsum2[i] = add2(lsum2[i], s2[i][0]);
            lsum2[i] = add2(lsum2[i], s2[i][1]);
        }

        // stage P (packed, 16B store)
        #pragma unroll
        for (int i = 0; i < 8; i++) {
            ulonglong2 w; w.x = s2[i][0]; w.y = s2[i][1];
            *(ulonglong2*)&Ps[(8 * ty + i) * 68 + 4 * tx] = w;
        }
        __syncthreads();

        // O += P * V  (unnormalized)
        #pragma unroll 2
        for (int t4 = 0; t4 < 64; t4 += 4) {
            float4 p4[8];
            #pragma unroll
            for (int i = 0; i < 8; i++) p4[i] = *(const float4*)&Ps[(8 * ty + i) * 68 + t4];
            const float* pp = (const float*)p4;
            #pragma unroll
            for (int tt = 0; tt < 4; tt++) {
                float4 vvv = *(const float4*)&Vs[(t4 + tt) * 68 + 4 * tx];
                const ull vlo = pk2(vvv.x, vvv.y), vhi = pk2(vvv.z, vvv.w);
                #pragma unroll
                for (int i = 0; i < 8; i++) {
                    const float ps = pp[i * 4 + tt];
                    const ull pd = pk2(ps, ps);
                    O2[i][0] = fma2(pd, vlo, O2[i][0]);
                    O2[i][1] = fma2(pd, vhi, O2[i][1]);
                }
            }
        }
    }

    // Partial epilogue: reduce row sums over 16 lanes, write raw O + sum.
    float* po = g_PO + ((size_t)(z * (B_ * NH_) + bh) * S_) * D_;
    float* pl = g_PL + (size_t)(z * (B_ * NH_) + bh) * S_;
    #pragma unroll
    for (int i = 0; i < 8; i++) {
        float l0, l1;
        upk2(lsum2[i], l0, l1);
        float rs = l0 + l1;
        rs += __shfl_xor_sync(0xffffffffu, rs, 1);
        rs += __shfl_xor_sync(0xffffffffu, rs, 2);
        rs += __shfl_xor_sync(0xffffffffu, rs, 4);
        rs += __shfl_xor_sync(0xffffffffu, rs, 8);
        const int srow = q0 + 8 * ty + i;
        float o0, o1, o2, o3;
        upk2(O2[i][0], o0, o1); upk2(O2[i][1], o2, o3);
        float4 v; v.x = o0; v.y = o1; v.z = o2; v.w = o3;
        *(float4*)(po + (size_t)srow * D_ + 4 * tx) = v;
        if (tx == 0) pl[srow] = rs;
    }
}

// ---------------------------------------------------------------------------
// Kernel 3: combine split-KV partials. out = (sum_z O_z) / (sum_z l_z).
// ---------------------------------------------------------------------------
__global__ __launch_bounds__(256) void reduce_kernel(float* __restrict__ out)
{
    const int idx = blockIdx.x * 256 + threadIdx.x;
    const int bh  = idx >> 15;
    const int rem = idx & 32767;
    const int s   = rem >> 4;
    const int d4  = (rem & 15) * 4;

    const size_t stride_o = (size_t)(B_ * NH_) * S_ * D_;
    const size_t stride_l = (size_t)(B_ * NH_) * S_;
    const size_t obase = ((size_t)bh * S_ + s) * D_ + d4;
    const size_t lbase = (size_t)bh * S_ + s;

    const float l = g_PL[lbase] + g_PL[stride_l + lbase] + g_PL[2 * stride_l + lbase];
    const float inv = 1.f / l;

    float4 a = *(const float4*)(g_PO + obase);
    float4 b = *(const float4*)(g_PO + stride_o + obase);
    float4 c = *(const float4*)(g_PO + 2 * stride_o + obase);

    float4 v;
    v.x = (a.x + b.x + c.x) * inv;
    v.y = (a.y + b.y + c.y) * inv;
    v.z = (a.z + b.z + c.z) * inv;
    v.w = (a.w + b.w + c.w) * inv;

    const int bi = bh / NH_, h = bh % NH_;
    *(float4*)(out + ((size_t)(bi * S_ + s)) * (NH_ * D_) + h * D_ + d4) = v;
}

// ---------------------------------------------------------------------------
extern "C" void kernel_launch(void* const* d_in, const int* in_sizes, int n_in,
                              void* d_out, int out_size)
{
    const float* e1 = (const float*)d_in[0];
    const float* e2 = (const float*)d_in[1];
    const float* e3 = (const float*)d_in[2];
    const float* Wq = (const float*)d_in[3];
    const float* bq = (const float*)d_in[4];
    const float* Wk = (const float*)d_in[5];
    const float* bk = (const float*)d_in[6];
    const float* Wv = (const float*)d_in[7];
    const float* bv = (const float*)d_in[8];
    float* out = (float*)d_out;

    const int attn_smem = (128 + 64 + 64 + 128) * 68 * 4;   // 104448
    cudaFuncSetAttribute(attn_kernel, cudaFuncAttributeMaxDynamicSharedMemorySize, attn_smem);

    dim3 ggrid(6, 64, 3);
    qkv_kernel<<<ggrid, 128>>>(e1, e2, e3, Wq, bq, Wk, bk, Wv, bv);

    dim3 agrid(S_ / 128, B_ * NH_, NZ_);
    attn_kernel<<<agrid, 256, attn_smem>>>();

    const int n4 = B_ * NH_ * S_ * (D_ / 4);     // 1572864
    reduce_kernel<<<n4 / 256, 256>>>(out);
}